// round 1
// baseline (speedup 1.0000x reference)
#include <cuda_runtime.h>

// CapsuleLayer dynamic routing, algebraically collapsed:
//   b[n,m] = x[n,:] @ Pacc[:,m]   (Pacc accumulates W@v across iterations)
//   s[m,:] = (1/Z) (e^T x) W[:,m,:],  v = squash(s),  Pacc[:,m] += W[:,m,:] v
// u_hat (268MB) is never materialized. Softmax stabilized by the
// Cauchy-Schwarz bound max_n |l| <= max_n||x_n|| * ||Pacc_col|| (no max pass).

#define NROW    2048
#define DIN     16
#define XSTRIDE 20
#define THREADS 512

struct Smem {
  float xs[NROW * XSTRIDE];   // padded x rows (float4-aligned, conflict-floor)
  float Wdc[16 * 16 * 16];    // [ml][d][c]
  float Wcd[16 * 16 * 16];    // [ml][c][d]
  float Pacc[16 * 16];        // [ml][d]
  float party[2 * 16 * 16];   // [chunk][ml][d]
  float partZ[2 * 16];        // [chunk][ml]
  float wpart[16 * 16];       // per-warp partial column sums of x
  float wmax[16];             // per-warp max row-norm^2
  float sumx[16];             // sum over n of x[n,d]
  float vbuf[16 * 16];        // [ml][c]
  float bnd[16];              // softmax shift bound per ml
  float mxnorm;
  float pad[3];
};

__device__ __forceinline__ unsigned long long mul2(unsigned long long a, unsigned long long b) {
  unsigned long long d; asm("mul.rn.f32x2 %0, %1, %2;" : "=l"(d) : "l"(a), "l"(b)); return d;
}
__device__ __forceinline__ unsigned long long add2(unsigned long long a, unsigned long long b) {
  unsigned long long d; asm("add.rn.f32x2 %0, %1, %2;" : "=l"(d) : "l"(a), "l"(b)); return d;
}
__device__ __forceinline__ unsigned long long fma2(unsigned long long a, unsigned long long b,
                                                   unsigned long long c) {
  unsigned long long d; asm("fma.rn.f32x2 %0, %1, %2, %3;" : "=l"(d) : "l"(a), "l"(b), "l"(c)); return d;
}
__device__ __forceinline__ unsigned long long pack2(float x) {
  unsigned long long d; asm("mov.b64 %0, {%1, %1};" : "=l"(d) : "f"(x)); return d;
}
__device__ __forceinline__ float hadd2(unsigned long long a) {
  float lo, hi; asm("mov.b64 {%0, %1}, %2;" : "=f"(lo), "=f"(hi) : "l"(a)); return lo + hi;
}

__global__ void __launch_bounds__(THREADS, 1)
caps_routing_kernel(const float* __restrict__ X, const float* __restrict__ Wg,
                    float* __restrict__ Y) {
  extern __shared__ char smraw[];
  Smem* sm = reinterpret_cast<Smem*>(smraw);
  const int tid  = threadIdx.x;
  const int lane = tid & 31;
  const int w    = tid >> 5;
  const int b    = blockIdx.x >> 1;
  const int m0   = (blockIdx.x & 1) * 16;

  if (tid < 256) sm->Pacc[tid] = 0.f;
  if (tid < 16)  sm->bnd[tid]  = 0.f;

  // ---- Load x tile (128KB) into padded smem; fold in column sums + max row norm ----
  const float4* Xb = reinterpret_cast<const float4*>(X + (size_t)b * NROW * DIN);
  const int q = tid & 3;  // which quarter of a row this thread loads (constant)
  float4 s4 = make_float4(0.f, 0.f, 0.f, 0.f);
  float mloc = 0.f;
#pragma unroll
  for (int i = 0; i < 16; ++i) {
    int idx = tid + THREADS * i;
    int n = idx >> 2;
    float4 v = Xb[idx];
    *reinterpret_cast<float4*>(&sm->xs[n * XSTRIDE + q * 4]) = v;
    s4.x += v.x; s4.y += v.y; s4.z += v.z; s4.w += v.w;
    float qd = v.x * v.x + v.y * v.y + v.z * v.z + v.w * v.w;
    qd += __shfl_xor_sync(0xffffffffu, qd, 1);
    qd += __shfl_xor_sync(0xffffffffu, qd, 2);   // full row norm^2 (4 lanes/row)
    mloc = fmaxf(mloc, qd);
  }
#pragma unroll
  for (int off = 4; off < 32; off <<= 1) {
    s4.x += __shfl_xor_sync(0xffffffffu, s4.x, off);
    s4.y += __shfl_xor_sync(0xffffffffu, s4.y, off);
    s4.z += __shfl_xor_sync(0xffffffffu, s4.z, off);
    s4.w += __shfl_xor_sync(0xffffffffu, s4.w, off);
    mloc = fmaxf(mloc, __shfl_xor_sync(0xffffffffu, mloc, off));
  }
  if (lane < 4) *reinterpret_cast<float4*>(&sm->wpart[w * 16 + lane * 4]) = s4;
  if (lane == 0) sm->wmax[w] = mloc;

  // ---- Load W slices for our 16 capsules in two layouts ----
#pragma unroll
  for (int i = 0; i < 8; ++i) {
    int idx2 = tid + THREADS * i;         // [ml][d][c]
    int ml = idx2 >> 8, d = (idx2 >> 4) & 15, c = idx2 & 15;
    float val = Wg[d * 512 + (m0 + ml) * 16 + c];
    sm->Wdc[idx2] = val;
    sm->Wcd[ml * 256 + c * 16 + d] = val;
  }
  __syncthreads();

  if (tid < 16) {
    float s = 0.f;
#pragma unroll
    for (int ww = 0; ww < 16; ++ww) s += sm->wpart[ww * 16 + tid];
    sm->sumx[tid] = s;
  }
  if (tid == 16) {
    float mx = 0.f;
#pragma unroll
    for (int ww = 0; ww < 16; ++ww) mx = fmaxf(mx, sm->wmax[ww]);
    sm->mxnorm = sqrtf(mx);
  }

  const int g = w & 7;        // m-pair group
  const int chunk = w >> 3;   // row chunk (0: rows 0-1023, 1: rows 1024-2047)
  const int mlA = 2 * g, mlB = 2 * g + 1;

  for (int it = 0; it < 3; ++it) {
    if (it > 0) {
      // ---- fused logit + softmax-exp + weighted-sum pass (f32x2 packed over d) ----
      unsigned long long pA[8], pB[8], yA[8], yB[8];
#pragma unroll
      for (int j = 0; j < 8; ++j) {
        pA[j] = *reinterpret_cast<const unsigned long long*>(&sm->Pacc[mlA * 16 + 2 * j]);
        pB[j] = *reinterpret_cast<const unsigned long long*>(&sm->Pacc[mlB * 16 + 2 * j]);
        yA[j] = 0ull; yB[j] = 0ull;
      }
      const float bndA = sm->bnd[mlA], bndB = sm->bnd[mlB];
      float ZA = 0.f, ZB = 0.f;
      const int nbase = chunk * 1024 + lane;
#pragma unroll 2
      for (int step = 0; step < 32; ++step) {
        const ulonglong2* xp =
            reinterpret_cast<const ulonglong2*>(&sm->xs[(nbase + step * 32) * XSTRIDE]);
        ulonglong2 q0 = xp[0], q1 = xp[1], q2 = xp[2], q3 = xp[3];
        unsigned long long xx[8];
        xx[0] = q0.x; xx[1] = q0.y; xx[2] = q1.x; xx[3] = q1.y;
        xx[4] = q2.x; xx[5] = q2.y; xx[6] = q3.x; xx[7] = q3.y;

        unsigned long long a0 = mul2(xx[0], pA[0]);
        unsigned long long a1 = mul2(xx[1], pA[1]);
        unsigned long long b0 = mul2(xx[0], pB[0]);
        unsigned long long b1 = mul2(xx[1], pB[1]);
#pragma unroll
        for (int j = 1; j < 4; ++j) {
          a0 = fma2(xx[2 * j],     pA[2 * j],     a0);
          a1 = fma2(xx[2 * j + 1], pA[2 * j + 1], a1);
          b0 = fma2(xx[2 * j],     pB[2 * j],     b0);
          b1 = fma2(xx[2 * j + 1], pB[2 * j + 1], b1);
        }
        float lA = hadd2(add2(a0, a1));
        float lB = hadd2(add2(b0, b1));
        float eA = __expf(lA - bndA);
        float eB = __expf(lB - bndB);
        ZA += eA; ZB += eB;
        unsigned long long eA2 = pack2(eA), eB2 = pack2(eB);
#pragma unroll
        for (int j = 0; j < 8; ++j) {
          yA[j] = fma2(eA2, xx[j], yA[j]);
          yB[j] = fma2(eB2, xx[j], yB[j]);
        }
      }
      // warp-reduce partials
#pragma unroll
      for (int off = 16; off >= 1; off >>= 1) {
        ZA += __shfl_xor_sync(0xffffffffu, ZA, off);
        ZB += __shfl_xor_sync(0xffffffffu, ZB, off);
#pragma unroll
        for (int j = 0; j < 8; ++j) {
          yA[j] = add2(yA[j], __shfl_xor_sync(0xffffffffu, yA[j], off));
          yB[j] = add2(yB[j], __shfl_xor_sync(0xffffffffu, yB[j], off));
        }
      }
      if (lane == 0) {
        sm->partZ[chunk * 16 + mlA] = ZA;
        sm->partZ[chunk * 16 + mlB] = ZB;
#pragma unroll
        for (int j = 0; j < 8; ++j) {
          *reinterpret_cast<unsigned long long*>(&sm->party[(chunk * 16 + mlA) * 16 + 2 * j]) = yA[j];
          *reinterpret_cast<unsigned long long*>(&sm->party[(chunk * 16 + mlB) * 16 + 2 * j]) = yB[j];
        }
      }
    }
    __syncthreads();

    // ---- per-capsule epilogue: s = yW/Z, squash, Pacc += W v, new bound ----
    if (w < 8) {
      const int mm  = lane >> 4;
      const int idx = lane & 15;
      const int ml  = 2 * g + mm;
      float Z = (it == 0) ? 2048.f : (sm->partZ[ml] + sm->partZ[16 + ml]);
      float s = 0.f;
#pragma unroll
      for (int d = 0; d < 16; ++d) {
        float yv = (it == 0) ? sm->sumx[d]
                             : (sm->party[ml * 16 + d] + sm->party[(16 + ml) * 16 + d]);
        s += yv * sm->Wdc[(ml * 16 + d) * 16 + idx];
      }
      s *= (1.f / Z);
      float nsq = s * s;
#pragma unroll
      for (int off = 1; off < 16; off <<= 1) nsq += __shfl_xor_sync(0xffffffffu, nsq, off);
      float norm = sqrtf(nsq);
      float fac  = nsq / ((1.f + nsq) * (norm + 1e-7f));
      float v    = s * fac;
      if (it == 2) {
        Y[(size_t)b * 512 + (m0 + ml) * 16 + idx] = v;
      } else {
        sm->vbuf[ml * 16 + idx] = v;
        __syncwarp();
        float pd = 0.f;
#pragma unroll
        for (int c = 0; c < 16; ++c)
          pd += sm->Wcd[(ml * 16 + c) * 16 + idx] * sm->vbuf[ml * 16 + c];
        float pn = sm->Pacc[ml * 16 + idx] + pd;
        sm->Pacc[ml * 16 + idx] = pn;
        float cn = pn * pn;
#pragma unroll
        for (int off = 1; off < 16; off <<= 1) cn += __shfl_xor_sync(0xffffffffu, cn, off);
        if (idx == 0) sm->bnd[ml] = sqrtf(cn) * sm->mxnorm;
      }
    }
    __syncthreads();
  }
}

extern "C" void kernel_launch(void* const* d_in, const int* in_sizes, int n_in,
                              void* d_out, int out_size) {
  (void)in_sizes; (void)n_in; (void)out_size;
  const float* X  = (const float*)d_in[0];   // inputs (64, 2048, 16)
  const float* Wg = (const float*)d_in[1];   // W (16, 32, 16)
  float* Y = (float*)d_out;                  // v (64, 32, 16)
  cudaFuncSetAttribute(caps_routing_kernel,
                       cudaFuncAttributeMaxDynamicSharedMemorySize, (int)sizeof(Smem));
  caps_routing_kernel<<<128, THREADS, sizeof(Smem)>>>(X, Wg, Y);
}

// round 2
// speedup vs baseline: 1.0743x; 1.0743x over previous
#include <cuda_runtime.h>

// CapsuleLayer dynamic routing, algebraically collapsed:
//   b[n,m] = x[n,:] @ Pacc[:,m]   (Pacc accumulates log2e * W@v across iterations)
//   s[m,:] = (1/Z) (e^T x) W[:,m,:],  v = squash(s),  Pacc[:,m] += log2e*W[:,m,:] v
// u_hat (268MB) never materialized. Softmax stabilized by Cauchy-Schwarz bound
// |l| <= max_n||x_n|| * ||Pacc_col||, computed in log2-domain so exp = EX2 only.
// R2: 8 warps x 4 capsules per warp (halves smem crossbar traffic vs C=2),
//     4-level warp reduction, ex2.approx.

#define NROW    2048
#define DIN     16
#define XSTRIDE 20
#define THREADS 256
#define LOG2E   1.4426950408889634f

struct Smem {
  float xs[NROW * XSTRIDE];     // padded x rows
  float Wdc[16 * 16 * 16];      // [ml][d][c]
  float Wcd[16 * 16 * 16];      // [ml][c][d]
  float Pacc[16 * 16];          // [ml][d]  (scaled by log2e)
  float party[2][2][16][16];    // [chunk][grp][ml][d]
  float partZ[2][2][16];        // [chunk][grp][ml]
  float wpart[8][16];           // per-warp partial column sums of x
  float wmax[8];                // per-warp max row-norm^2
  float sumx[16];               // sum over n of x[n,d]
  float vbuf[16 * 16];          // [ml][c]
  float bnd[16];                // softmax shift bound per ml (log2 domain)
  float mxnorm;
  float pad[3];
};

typedef unsigned long long ull;

__device__ __forceinline__ ull mul2(ull a, ull b) {
  ull d; asm("mul.rn.f32x2 %0, %1, %2;" : "=l"(d) : "l"(a), "l"(b)); return d;
}
__device__ __forceinline__ ull add2(ull a, ull b) {
  ull d; asm("add.rn.f32x2 %0, %1, %2;" : "=l"(d) : "l"(a), "l"(b)); return d;
}
__device__ __forceinline__ ull fma2(ull a, ull b, ull c) {
  ull d; asm("fma.rn.f32x2 %0, %1, %2, %3;" : "=l"(d) : "l"(a), "l"(b), "l"(c)); return d;
}
__device__ __forceinline__ ull pack2(float x) {
  ull d; asm("mov.b64 %0, {%1, %1};" : "=l"(d) : "f"(x)); return d;
}
__device__ __forceinline__ float hadd2(ull a) {
  float lo, hi; asm("mov.b64 {%0, %1}, %2;" : "=f"(lo), "=f"(hi) : "l"(a)); return lo + hi;
}
__device__ __forceinline__ float ex2f(float x) {
  float r; asm("ex2.approx.f32 %0, %1;" : "=f"(r) : "f"(x)); return r;
}

__global__ void __launch_bounds__(THREADS, 1)
caps_routing_kernel(const float* __restrict__ X, const float* __restrict__ Wg,
                    float* __restrict__ Y) {
  extern __shared__ char smraw[];
  Smem* sm = reinterpret_cast<Smem*>(smraw);
  const int tid  = threadIdx.x;
  const int lane = tid & 31;
  const int w    = tid >> 5;
  const int b    = blockIdx.x >> 1;
  const int m0   = (blockIdx.x & 1) * 16;

  sm->Pacc[tid] = 0.f;              // 256 entries, 256 threads
  if (tid < 16) sm->bnd[tid] = 0.f;

  // ---- Load x tile (128KB) into padded smem; fold in column sums + max row norm ----
  const float4* Xb = reinterpret_cast<const float4*>(X + (size_t)b * NROW * DIN);
  const int q = tid & 3;  // constant quarter of a row per thread
  float4 s4 = make_float4(0.f, 0.f, 0.f, 0.f);
  float mloc = 0.f;
#pragma unroll
  for (int i = 0; i < 32; ++i) {
    int idx = tid + THREADS * i;
    int n = idx >> 2;
    float4 v = Xb[idx];
    *reinterpret_cast<float4*>(&sm->xs[n * XSTRIDE + q * 4]) = v;
    s4.x += v.x; s4.y += v.y; s4.z += v.z; s4.w += v.w;
    float qd = v.x * v.x + v.y * v.y + v.z * v.z + v.w * v.w;
    qd += __shfl_xor_sync(0xffffffffu, qd, 1);
    qd += __shfl_xor_sync(0xffffffffu, qd, 2);
    mloc = fmaxf(mloc, qd);
  }
#pragma unroll
  for (int off = 4; off < 32; off <<= 1) {
    s4.x += __shfl_xor_sync(0xffffffffu, s4.x, off);
    s4.y += __shfl_xor_sync(0xffffffffu, s4.y, off);
    s4.z += __shfl_xor_sync(0xffffffffu, s4.z, off);
    s4.w += __shfl_xor_sync(0xffffffffu, s4.w, off);
    mloc = fmaxf(mloc, __shfl_xor_sync(0xffffffffu, mloc, off));
  }
  if (lane < 4) *reinterpret_cast<float4*>(&sm->wpart[w][lane * 4]) = s4;
  if (lane == 0) sm->wmax[w] = mloc;

  // ---- Load W slices in two layouts ----
#pragma unroll
  for (int i = 0; i < 16; ++i) {
    int idx2 = tid + THREADS * i;         // [ml][d][c]
    int ml = idx2 >> 8, d = (idx2 >> 4) & 15, c = idx2 & 15;
    float val = Wg[d * 512 + (m0 + ml) * 16 + c];
    sm->Wdc[idx2] = val;
    sm->Wcd[ml * 256 + c * 16 + d] = val;
  }
  __syncthreads();

  if (tid < 16) {
    float s = 0.f;
#pragma unroll
    for (int ww = 0; ww < 8; ++ww) s += sm->wpart[ww][tid];
    sm->sumx[tid] = s;
  }
  if (tid == 16) {
    float mx = 0.f;
#pragma unroll
    for (int ww = 0; ww < 8; ++ww) mx = fmaxf(mx, sm->wmax[ww]);
    sm->mxnorm = sqrtf(mx);
  }

  const int g     = w & 3;      // capsule group of 4
  const int chunk = w >> 2;     // row chunk (0: 0-1023, 1: 1024-2047)
  const int mlb   = 4 * g;

  for (int it = 0; it < 3; ++it) {
    if (it > 0) {
      // ---- fused logit(log2) + EX2 + weighted-sum pass, 4 capsules per warp ----
      ull p[4][8], y[4][8];
      float bndv[4], Z[4];
#pragma unroll
      for (int c = 0; c < 4; ++c) {
#pragma unroll
        for (int j = 0; j < 8; ++j) {
          p[c][j] = *reinterpret_cast<const ull*>(&sm->Pacc[(mlb + c) * 16 + 2 * j]);
          y[c][j] = 0ull;
        }
        bndv[c] = sm->bnd[mlb + c];
        Z[c] = 0.f;
      }
      const int nbase = chunk * 1024 + lane;
#pragma unroll 2
      for (int step = 0; step < 32; ++step) {
        const ulonglong2* xp =
            reinterpret_cast<const ulonglong2*>(&sm->xs[(nbase + step * 32) * XSTRIDE]);
        ulonglong2 q0 = xp[0], q1 = xp[1], q2 = xp[2], q3 = xp[3];
        ull xx[8];
        xx[0] = q0.x; xx[1] = q0.y; xx[2] = q1.x; xx[3] = q1.y;
        xx[4] = q2.x; xx[5] = q2.y; xx[6] = q3.x; xx[7] = q3.y;
#pragma unroll
        for (int c = 0; c < 4; ++c) {
          ull a0 = mul2(xx[0], p[c][0]);
          ull a1 = mul2(xx[1], p[c][1]);
#pragma unroll
          for (int j = 1; j < 4; ++j) {
            a0 = fma2(xx[2 * j],     p[c][2 * j],     a0);
            a1 = fma2(xx[2 * j + 1], p[c][2 * j + 1], a1);
          }
          float l = hadd2(add2(a0, a1));
          float e = ex2f(l - bndv[c]);
          Z[c] += e;
          ull e2 = pack2(e);
#pragma unroll
          for (int j = 0; j < 8; ++j) y[c][j] = fma2(e2, xx[j], y[c][j]);
        }
      }
      // 4-level warp reduction -> 2 partials (lanes 0,1 mod 2)
#pragma unroll
      for (int off = 16; off >= 2; off >>= 1) {
#pragma unroll
        for (int c = 0; c < 4; ++c) {
          Z[c] += __shfl_xor_sync(0xffffffffu, Z[c], off);
#pragma unroll
          for (int j = 0; j < 8; ++j)
            y[c][j] = add2(y[c][j], __shfl_xor_sync(0xffffffffu, y[c][j], off));
        }
      }
      if (lane < 2) {
#pragma unroll
        for (int c = 0; c < 4; ++c) {
          sm->partZ[chunk][lane][mlb + c] = Z[c];
#pragma unroll
          for (int j = 0; j < 8; ++j)
            *reinterpret_cast<ull*>(&sm->party[chunk][lane][mlb + c][2 * j]) = y[c][j];
        }
      }
    }
    __syncthreads();

    // ---- per-capsule epilogue: s = yW/Z, squash, Pacc += log2e * W v, new bound ----
    {
      const int ml  = w * 2 + (lane >> 4);
      const int idx = lane & 15;
      float Z = (it == 0) ? 2048.f
                          : (sm->partZ[0][0][ml] + sm->partZ[0][1][ml] +
                             sm->partZ[1][0][ml] + sm->partZ[1][1][ml]);
      float s = 0.f;
#pragma unroll
      for (int d = 0; d < 16; ++d) {
        float yv = (it == 0) ? sm->sumx[d]
                             : (sm->party[0][0][ml][d] + sm->party[0][1][ml][d] +
                                sm->party[1][0][ml][d] + sm->party[1][1][ml][d]);
        s += yv * sm->Wdc[(ml * 16 + d) * 16 + idx];
      }
      s *= (1.f / Z);
      float nsq = s * s;
#pragma unroll
      for (int off = 1; off < 16; off <<= 1) nsq += __shfl_xor_sync(0xffffffffu, nsq, off);
      float norm = sqrtf(nsq);
      float fac  = nsq / ((1.f + nsq) * (norm + 1e-7f));
      float v    = s * fac;
      if (it == 2) {
        Y[(size_t)b * 512 + (m0 + ml) * 16 + idx] = v;
      } else {
        sm->vbuf[ml * 16 + idx] = v;
        __syncwarp();
        float pd = 0.f;
#pragma unroll
        for (int c = 0; c < 16; ++c)
          pd += sm->Wcd[(ml * 16 + c) * 16 + idx] * sm->vbuf[ml * 16 + c];
        float pn = sm->Pacc[ml * 16 + idx] + LOG2E * pd;
        sm->Pacc[ml * 16 + idx] = pn;
        float cn = pn * pn;
#pragma unroll
        for (int off = 1; off < 16; off <<= 1) cn += __shfl_xor_sync(0xffffffffu, cn, off);
        if (idx == 0) sm->bnd[ml] = sqrtf(cn) * sm->mxnorm;
      }
    }
    __syncthreads();
  }
}

extern "C" void kernel_launch(void* const* d_in, const int* in_sizes, int n_in,
                              void* d_out, int out_size) {
  (void)in_sizes; (void)n_in; (void)out_size;
  const float* X  = (const float*)d_in[0];   // inputs (64, 2048, 16)
  const float* Wg = (const float*)d_in[1];   // W (16, 32, 16)
  float* Y = (float*)d_out;                  // v (64, 32, 16)
  cudaFuncSetAttribute(caps_routing_kernel,
                       cudaFuncAttributeMaxDynamicSharedMemorySize, (int)sizeof(Smem));
  caps_routing_kernel<<<128, THREADS, sizeof(Smem)>>>(X, Wg, Y);
}